// round 2
// baseline (speedup 1.0000x reference)
#include <cuda_runtime.h>
#include <cuda_bf16.h>
#include <math.h>

// Problem constants
#define BB 4
#define SS 2048
#define DD 1024
#define HH 16
#define HD 64
#define MROWS (BB * SS)   // 8192

// Scratch (device globals: allocation-free)
__device__ float g_Q[BB * HH * SS * HD];
__device__ float g_K[BB * HH * SS * HD];
__device__ float g_V[BB * HH * SS * HD];
__device__ float g_ctx[BB * SS * DD];

// ---------------------------------------------------------------------------
// SGEMM (NT): C[m,n] = sum_k A[m,k] * W[n,k] + bias[n]
// A: [M,K] row-major, W: [N,K] row-major. 128x128 tile, KT=8, 256 threads,
// 8x8 microtile per thread. mode 0: C row-major [M,N]; mode 1: scatter to
// [B,H,S,hd] with m=(b,s), n=(h,hd).
// ---------------------------------------------------------------------------
#define TILE 128
#define KT 8

__global__ __launch_bounds__(256) void gemm_nt(
    const float* __restrict__ A, const float* __restrict__ W,
    const float* __restrict__ bias, float* __restrict__ C,
    int M, int N, int K, int mode)
{
    __shared__ float As[KT][TILE + 4];
    __shared__ float Bs[KT][TILE + 4];

    const int tid = threadIdx.x;
    const int bm = blockIdx.y * TILE;
    const int bn = blockIdx.x * TILE;
    const int tx = tid & 15;     // 0..15
    const int ty = tid >> 4;     // 0..15

    const int lrow = tid >> 1;       // 0..127
    const int lk4  = (tid & 1) * 4;  // 0 or 4

    float acc[8][8];
#pragma unroll
    for (int i = 0; i < 8; i++)
#pragma unroll
        for (int j = 0; j < 8; j++) acc[i][j] = 0.0f;

    const float* Aptr = A + (size_t)(bm + lrow) * K + lk4;
    const float* Wptr = W + (size_t)(bn + lrow) * K + lk4;

    for (int k0 = 0; k0 < K; k0 += KT) {
        float4 av = *(const float4*)(Aptr + k0);
        float4 bv = *(const float4*)(Wptr + k0);
        __syncthreads();
        As[lk4 + 0][lrow] = av.x; As[lk4 + 1][lrow] = av.y;
        As[lk4 + 2][lrow] = av.z; As[lk4 + 3][lrow] = av.w;
        Bs[lk4 + 0][lrow] = bv.x; Bs[lk4 + 1][lrow] = bv.y;
        Bs[lk4 + 2][lrow] = bv.z; Bs[lk4 + 3][lrow] = bv.w;
        __syncthreads();

#pragma unroll
        for (int kk = 0; kk < KT; kk++) {
            float a[8], b[8];
#pragma unroll
            for (int i = 0; i < 8; i++) a[i] = As[kk][ty * 8 + i];
#pragma unroll
            for (int j = 0; j < 8; j++) b[j] = Bs[kk][tx * 8 + j];
#pragma unroll
            for (int i = 0; i < 8; i++)
#pragma unroll
                for (int j = 0; j < 8; j++)
                    acc[i][j] = fmaf(a[i], b[j], acc[i][j]);
        }
    }

    // Epilogue
#pragma unroll
    for (int i = 0; i < 8; i++) {
        const int m = bm + ty * 8 + i;
#pragma unroll
        for (int j4 = 0; j4 < 2; j4++) {
            const int n = bn + tx * 8 + j4 * 4;
            float4 v;
            v.x = acc[i][j4 * 4 + 0] + bias[n + 0];
            v.y = acc[i][j4 * 4 + 1] + bias[n + 1];
            v.z = acc[i][j4 * 4 + 2] + bias[n + 2];
            v.w = acc[i][j4 * 4 + 3] + bias[n + 3];
            if (mode == 0) {
                *(float4*)(C + (size_t)m * N + n) = v;
            } else {
                const int b  = m >> 11;       // m / 2048
                const int s  = m & 2047;
                const int h  = n >> 6;        // n / 64
                const int hd = n & 63;
                float* dst = C + (((size_t)(b * HH + h) * SS + s) * HD + hd);
                *(float4*)dst = v;
            }
        }
    }
}

// ---------------------------------------------------------------------------
// RoPE, in-place on [B,H,S,hd]. Pair (p, p+32) per thread.
// ---------------------------------------------------------------------------
__global__ void rope_kernel(float* __restrict__ X,
                            const float* __restrict__ cosb,
                            const float* __restrict__ sinb)
{
    const int gid = blockIdx.x * blockDim.x + threadIdx.x;
    const int p = gid & 31;
    const int r = gid >> 5;               // row in [B*H*S)
    const int s = r & (SS - 1);
    const float c1 = cosb[s * HD + p];
    const float s1 = sinb[s * HD + p];
    const float c2 = cosb[s * HD + p + 32];
    const float s2 = sinb[s * HD + p + 32];
    float* row = X + (size_t)r * HD;
    const float x1 = row[p];
    const float x2 = row[p + 32];
    row[p]      = x1 * c1 - x2 * s1;
    row[p + 32] = x2 * c2 + x1 * s2;
}

// ---------------------------------------------------------------------------
// Causal flash attention, fp32. 1 block = 64 query rows of one (b,h);
// 1 thread = 1 query row. Online softmax in 16-key chunks.
// Writes ctx in [B,S,D] layout.
// ---------------------------------------------------------------------------
#define FBM 64
#define FBN 64

__global__ __launch_bounds__(64) void flash_kernel(
    const float* __restrict__ Q, const float* __restrict__ K,
    const float* __restrict__ V, float* __restrict__ ctx)
{
    __shared__ float Ks[FBN * HD];
    __shared__ float Vs[FBN * HD];

    const int t  = threadIdx.x;       // 0..63 (query row within block)
    const int qb = blockIdx.x;        // query tile
    const int bh = blockIdx.y;        // b*H + h
    const int qidx = qb * FBM + t;

    const float* Qp = Q + (size_t)bh * SS * HD;
    const float* Kp = K + (size_t)bh * SS * HD;
    const float* Vp = V + (size_t)bh * SS * HD;

    // Load q row to registers
    float q[HD];
    {
        const float4* qg = (const float4*)(Qp + (size_t)qidx * HD);
#pragma unroll
        for (int i = 0; i < HD / 4; i++) {
            float4 v = qg[i];
            q[4 * i + 0] = v.x; q[4 * i + 1] = v.y;
            q[4 * i + 2] = v.z; q[4 * i + 3] = v.w;
        }
    }

    float o[HD];
#pragma unroll
    for (int d = 0; d < HD; d++) o[d] = 0.0f;
    float m = -1e30f;
    float l = 0.0f;

    for (int kt = 0; kt <= qb; kt++) {
        __syncthreads();
        // Cooperative coalesced load of K,V tile (1024 float4 each, 64 threads)
        {
            const float4* kg = (const float4*)(Kp + (size_t)kt * FBN * HD);
            const float4* vg = (const float4*)(Vp + (size_t)kt * FBN * HD);
            float4* ks4 = (float4*)Ks;
            float4* vs4 = (float4*)Vs;
#pragma unroll
            for (int i = 0; i < 16; i++) {
                ks4[i * 64 + t] = kg[i * 64 + t];
                vs4[i * 64 + t] = vg[i * 64 + t];
            }
        }
        __syncthreads();

#pragma unroll 1
        for (int c = 0; c < 4; c++) {
            float sc[16];
#pragma unroll
            for (int j = 0; j < 16; j++) {
                const int jj = c * 16 + j;
                const float4* kr = (const float4*)(Ks + jj * HD);
                float a0 = 0.f, a1 = 0.f, a2 = 0.f, a3 = 0.f;
#pragma unroll
                for (int d4 = 0; d4 < 16; d4++) {
                    float4 kv = kr[d4];
                    a0 = fmaf(q[4 * d4 + 0], kv.x, a0);
                    a1 = fmaf(q[4 * d4 + 1], kv.y, a1);
                    a2 = fmaf(q[4 * d4 + 2], kv.z, a2);
                    a3 = fmaf(q[4 * d4 + 3], kv.w, a3);
                }
                const int kidx = kt * FBN + jj;
                sc[j] = (kidx <= qidx) ? (a0 + a1 + a2 + a3) * 0.125f : -1e30f;
            }
            // Online softmax update
            float mloc = sc[0];
#pragma unroll
            for (int j = 1; j < 16; j++) mloc = fmaxf(mloc, sc[j]);
            const float mnew = fmaxf(m, mloc);
            const float corr = __expf(m - mnew);
            m = mnew;
            l *= corr;
#pragma unroll
            for (int d = 0; d < HD; d++) o[d] *= corr;
#pragma unroll
            for (int j = 0; j < 16; j++) {
                const float p = __expf(sc[j] - mnew);
                l += p;
                const float4* vr = (const float4*)(Vs + (c * 16 + j) * HD);
#pragma unroll
                for (int d4 = 0; d4 < 16; d4++) {
                    float4 vv = vr[d4];
                    o[4 * d4 + 0] = fmaf(p, vv.x, o[4 * d4 + 0]);
                    o[4 * d4 + 1] = fmaf(p, vv.y, o[4 * d4 + 1]);
                    o[4 * d4 + 2] = fmaf(p, vv.z, o[4 * d4 + 2]);
                    o[4 * d4 + 3] = fmaf(p, vv.w, o[4 * d4 + 3]);
                }
            }
        }
    }

    const float inv = 1.0f / l;
    const int b = bh >> 4;
    const int h = bh & 15;
    float* dst = ctx + ((size_t)(b * SS + qidx)) * DD + h * HD;
#pragma unroll
    for (int d4 = 0; d4 < 16; d4++) {
        float4 v;
        v.x = o[4 * d4 + 0] * inv;
        v.y = o[4 * d4 + 1] * inv;
        v.z = o[4 * d4 + 2] * inv;
        v.w = o[4 * d4 + 3] * inv;
        *(float4*)(dst + 4 * d4) = v;
    }
}

// ---------------------------------------------------------------------------
// Launch
// ---------------------------------------------------------------------------
extern "C" void kernel_launch(void* const* d_in, const int* in_sizes, int n_in,
                              void* d_out, int out_size)
{
    const float* x    = (const float*)d_in[0];
    // d_in[1] = mask (causal; implemented analytically)
    const float* cosb = (const float*)d_in[2];
    const float* sinb = (const float*)d_in[3];
    const float* Wq = (const float*)d_in[4];
    const float* bq = (const float*)d_in[5];
    const float* Wk = (const float*)d_in[6];
    const float* bk = (const float*)d_in[7];
    const float* Wv = (const float*)d_in[8];
    const float* bv = (const float*)d_in[9];
    const float* Wo = (const float*)d_in[10];
    const float* bo = (const float*)d_in[11];
    float* out = (float*)d_out;

    float *Qb, *Kb, *Vb, *Cb;
    cudaGetSymbolAddress((void**)&Qb, g_Q);
    cudaGetSymbolAddress((void**)&Kb, g_K);
    cudaGetSymbolAddress((void**)&Vb, g_V);
    cudaGetSymbolAddress((void**)&Cb, g_ctx);

    dim3 gg(DD / TILE, MROWS / TILE);   // (8, 64)
    gemm_nt<<<gg, 256>>>(x, Wq, bq, Qb, MROWS, DD, DD, 1);
    gemm_nt<<<gg, 256>>>(x, Wk, bk, Kb, MROWS, DD, DD, 1);
    gemm_nt<<<gg, 256>>>(x, Wv, bv, Vb, MROWS, DD, DD, 1);

    const int rope_threads = BB * HH * SS * 32;
    rope_kernel<<<rope_threads / 256, 256>>>(Qb, cosb, sinb);
    rope_kernel<<<rope_threads / 256, 256>>>(Kb, cosb, sinb);

    dim3 fg(SS / FBM, BB * HH);         // (32, 64)
    flash_kernel<<<fg, 64>>>(Qb, Kb, Vb, Cb);

    gemm_nt<<<gg, 256>>>(Cb, Wo, bo, out, MROWS, DD, DD, 0);
}

// round 4
// speedup vs baseline: 1.5157x; 1.5157x over previous
#include <cuda_runtime.h>
#include <cuda_bf16.h>
#include <math.h>
#include <stdint.h>

// Problem constants
#define BB 4
#define SS 2048
#define DD 1024
#define HH 16
#define HD 64
#define MROWS (BB * SS)   // 8192

// ---------------------------------------------------------------------------
// Scratch (device globals: allocation-free)
// ---------------------------------------------------------------------------
__device__ float g_Q[BB * HH * SS * HD];
__device__ float g_K[BB * HH * SS * HD];
__device__ float g_V[BB * HH * SS * HD];
__device__ __align__(16) __nv_bfloat16 g_xh[MROWS * DD];
__device__ __align__(16) __nv_bfloat16 g_xl[MROWS * DD];
__device__ __align__(16) __nv_bfloat16 g_wh[4 * DD * DD];
__device__ __align__(16) __nv_bfloat16 g_wl[4 * DD * DD];
__device__ __align__(16) __nv_bfloat16 g_ch[MROWS * DD];
__device__ __align__(16) __nv_bfloat16 g_cl[MROWS * DD];

// ---------------------------------------------------------------------------
// Helpers
// ---------------------------------------------------------------------------
__device__ __forceinline__ uint32_t smem_u32(const void* p) {
    uint32_t a;
    asm("{ .reg .u64 t; cvta.to.shared.u64 t, %1; cvt.u32.u64 %0, t; }"
        : "=r"(a) : "l"(p));
    return a;
}

__device__ __forceinline__ void ldsm4(uint32_t* r, uint32_t addr) {
    asm volatile("ldmatrix.sync.aligned.m8n8.x4.shared.b16 {%0,%1,%2,%3}, [%4];"
                 : "=r"(r[0]), "=r"(r[1]), "=r"(r[2]), "=r"(r[3]) : "r"(addr));
}

__device__ __forceinline__ void mma16816(float* c, const uint32_t* a, const uint32_t* b) {
    asm volatile("mma.sync.aligned.m16n8k16.row.col.f32.bf16.bf16.f32 "
                 "{%0,%1,%2,%3}, {%4,%5,%6,%7}, {%8,%9}, {%0,%1,%2,%3};"
                 : "+f"(c[0]), "+f"(c[1]), "+f"(c[2]), "+f"(c[3])
                 : "r"(a[0]), "r"(a[1]), "r"(a[2]), "r"(a[3]), "r"(b[0]), "r"(b[1]));
}

__device__ __forceinline__ uint32_t pk2(__nv_bfloat16 a, __nv_bfloat16 b) {
    return (uint32_t)__bfloat16_as_ushort(a) | ((uint32_t)__bfloat16_as_ushort(b) << 16);
}

// ---------------------------------------------------------------------------
// fp32 -> (bf16 hi, bf16 lo) split, vectorized x4
// ---------------------------------------------------------------------------
__global__ __launch_bounds__(256) void split_kernel(
    const float4* __restrict__ src, uint2* __restrict__ hi, uint2* __restrict__ lo, int n4)
{
    int i = blockIdx.x * blockDim.x + threadIdx.x;
    if (i >= n4) return;
    float4 v = src[i];
    __nv_bfloat16 h0 = __float2bfloat16(v.x), h1 = __float2bfloat16(v.y);
    __nv_bfloat16 h2 = __float2bfloat16(v.z), h3 = __float2bfloat16(v.w);
    __nv_bfloat16 l0 = __float2bfloat16(v.x - __bfloat162float(h0));
    __nv_bfloat16 l1 = __float2bfloat16(v.y - __bfloat162float(h1));
    __nv_bfloat16 l2 = __float2bfloat16(v.z - __bfloat162float(h2));
    __nv_bfloat16 l3 = __float2bfloat16(v.w - __bfloat162float(h3));
    hi[i] = make_uint2(pk2(h0, h1), pk2(h2, h3));
    lo[i] = make_uint2(pk2(l0, l1), pk2(l2, l3));
}

// ---------------------------------------------------------------------------
// HMMA bf16-split GEMM (NT): C[m,n] = sum_k A[m,k]*W[n,k] + bias[n]
// A=Ah+Al [M,K] row-major bf16; W=Bh+Bl [N,K] row-major bf16.
// CTA 128x128, 8 warps (warp tile 64x32), K-chunk 32, double buffered smem.
// Rows padded to 80B -> conflict-free ldmatrix.
// mode 0: C row-major fp32 [M,N]; mode 1: scatter to [B,H,S,hd].
// ---------------------------------------------------------------------------
#define GK 32
#define NCHUNK (DD / GK)       // 32
#define ROWB 80                // 64B data + 16B pad
#define TILE_SB (128 * ROWB)   // 10240
#define BUF_SB (4 * TILE_SB)   // 40960 : Ah, Al, Bh, Bl
#define GEMM_SMEM (2 * BUF_SB) // 81920

__global__ __launch_bounds__(256) void gemm_mma(
    const __nv_bfloat16* __restrict__ Ah, const __nv_bfloat16* __restrict__ Al,
    const __nv_bfloat16* __restrict__ Bh, const __nv_bfloat16* __restrict__ Bl,
    const float* __restrict__ bias, float* __restrict__ C, int mode)
{
    extern __shared__ char sm[];
    const int tid  = threadIdx.x;
    const int wid  = tid >> 5;
    const int lane = tid & 31;
    const int bm = blockIdx.y * 128;
    const int bn = blockIdx.x * 128;
    const int warp_m = (wid & 1) * 64;
    const int warp_n = (wid >> 1) * 32;

    const uint32_t sb = smem_u32(sm);

    const char* gsrc[4] = {
        (const char*)(Ah + (size_t)bm * DD), (const char*)(Al + (size_t)bm * DD),
        (const char*)(Bh + (size_t)bn * DD), (const char*)(Bl + (size_t)bn * DD) };

    float acc[4][4][4];
#pragma unroll
    for (int i = 0; i < 4; i++)
#pragma unroll
        for (int j = 0; j < 4; j++)
#pragma unroll
            for (int q = 0; q < 4; q++) acc[i][j][q] = 0.0f;

    // chunk loader: 4 tiles x 512 segs of 16B, 2 per thread per tile
    auto load_chunk = [&](int c, int buf) {
        char* base = sm + buf * BUF_SB;
        const int koff = c * 64;   // bytes along K
#pragma unroll
        for (int t = 0; t < 4; t++) {
            const char* g = gsrc[t] + koff;
            char* s = base + t * TILE_SB;
#pragma unroll
            for (int i = 0; i < 2; i++) {
                int idx = i * 256 + tid;
                int row = idx >> 2, seg = idx & 3;
                uint4 v = *(const uint4*)(g + (size_t)row * 2048 + seg * 16);
                *(uint4*)(s + row * ROWB + seg * 16) = v;
            }
        }
    };

    load_chunk(0, 0);
    __syncthreads();

    const int lig = lane & 7;
    const int grp = lane >> 3;   // 0..3

    for (int c = 0; c < NCHUNK; c++) {
        const int cur = c & 1;
        if (c + 1 < NCHUNK) load_chunk(c + 1, cur ^ 1);

        const uint32_t bufb = sb + cur * BUF_SB;
#pragma unroll
        for (int ks = 0; ks < 2; ks++) {
            uint32_t aH[4][4], aL[4][4], bH[2][4], bL[2][4];
            // A fragments: groups (m0-7,k0),(m8-15,k0),(m0-7,k8),(m8-15,k8)
            {
                const int arow = warp_m + (grp & 1) * 8 + lig;
                const int aseg = 2 * ks + (grp >> 1);
                const uint32_t aoff = arow * ROWB + aseg * 16;
#pragma unroll
                for (int mi = 0; mi < 4; mi++) {
                    ldsm4(aH[mi], bufb + 0 * TILE_SB + aoff + mi * (16 * ROWB));
                    ldsm4(aL[mi], bufb + 1 * TILE_SB + aoff + mi * (16 * ROWB));
                }
            }
            // B fragments: groups (n0-7,k0),(n0-7,k8),(n8-15,k0),(n8-15,k8)
            {
                const int brow = warp_n + (grp >> 1) * 8 + lig;
                const int bseg = 2 * ks + (grp & 1);
                const uint32_t boff = brow * ROWB + bseg * 16;
#pragma unroll
                for (int ni = 0; ni < 2; ni++) {
                    ldsm4(bH[ni], bufb + 2 * TILE_SB + boff + ni * (16 * ROWB));
                    ldsm4(bL[ni], bufb + 3 * TILE_SB + boff + ni * (16 * ROWB));
                }
            }
#pragma unroll
            for (int mi = 0; mi < 4; mi++)
#pragma unroll
                for (int nj = 0; nj < 4; nj++) {
                    const int ni = nj >> 1, pr = (nj & 1) * 2;
                    mma16816(acc[mi][nj], aH[mi], &bH[ni][pr]);   // Ah*Bh
                    mma16816(acc[mi][nj], aH[mi], &bL[ni][pr]);   // Ah*Bl
                    mma16816(acc[mi][nj], aL[mi], &bH[ni][pr]);   // Al*Bh
                }
        }
        __syncthreads();
    }

    // Epilogue: c frag (m16n8): c0,c1 @ (m + lane/4, n + 2*(lane%4)); c2,c3 @ m+8
    const int mrow = lane >> 2;
    const int ncol = 2 * (lane & 3);
#pragma unroll
    for (int mi = 0; mi < 4; mi++) {
#pragma unroll
        for (int nj = 0; nj < 4; nj++) {
            const int m0 = bm + warp_m + mi * 16 + mrow;
            const int n  = bn + warp_n + nj * 8 + ncol;
            const float b0 = bias[n], b1 = bias[n + 1];
#pragma unroll
            for (int half = 0; half < 2; half++) {
                const int m = m0 + half * 8;
                float2 v;
                v.x = acc[mi][nj][2 * half + 0] + b0;
                v.y = acc[mi][nj][2 * half + 1] + b1;
                float* dst;
                if (mode == 0) {
                    dst = C + (size_t)m * DD + n;
                } else {
                    const int b = m >> 11, s = m & 2047;
                    const int h = n >> 6, hd0 = n & 63;
                    dst = C + (((size_t)(b * HH + h) * SS + s) * HD + hd0);
                }
                *(float2*)dst = v;
            }
        }
    }
}

// ---------------------------------------------------------------------------
// RoPE, in-place on [B,H,S,hd]
// ---------------------------------------------------------------------------
__global__ void rope_kernel(float* __restrict__ X,
                            const float* __restrict__ cosb,
                            const float* __restrict__ sinb)
{
    const int gid = blockIdx.x * blockDim.x + threadIdx.x;
    const int p = gid & 31;
    const int r = gid >> 5;
    const int s = r & (SS - 1);
    const float c1 = cosb[s * HD + p];
    const float s1 = sinb[s * HD + p];
    const float c2 = cosb[s * HD + p + 32];
    const float s2 = sinb[s * HD + p + 32];
    float* row = X + (size_t)r * HD;
    const float x1 = row[p];
    const float x2 = row[p + 32];
    row[p]      = x1 * c1 - x2 * s1;
    row[p + 32] = x2 * c2 + x1 * s2;
}

// ---------------------------------------------------------------------------
// Causal flash attention, fp32; epilogue writes ctx as bf16 hi/lo splits.
// ---------------------------------------------------------------------------
#define FBM 64
#define FBN 64

__global__ __launch_bounds__(64) void flash_kernel(
    const float* __restrict__ Q, const float* __restrict__ K,
    const float* __restrict__ V,
    __nv_bfloat16* __restrict__ ctx_h, __nv_bfloat16* __restrict__ ctx_l)
{
    __shared__ float Ks[FBN * HD];
    __shared__ float Vs[FBN * HD];

    const int t  = threadIdx.x;
    const int qb = blockIdx.x;
    const int bh = blockIdx.y;
    const int qidx = qb * FBM + t;

    const float* Qp = Q + (size_t)bh * SS * HD;
    const float* Kp = K + (size_t)bh * SS * HD;
    const float* Vp = V + (size_t)bh * SS * HD;

    float q[HD];
    {
        const float4* qg = (const float4*)(Qp + (size_t)qidx * HD);
#pragma unroll
        for (int i = 0; i < HD / 4; i++) {
            float4 v = qg[i];
            q[4 * i + 0] = v.x; q[4 * i + 1] = v.y;
            q[4 * i + 2] = v.z; q[4 * i + 3] = v.w;
        }
    }

    float o[HD];
#pragma unroll
    for (int d = 0; d < HD; d++) o[d] = 0.0f;
    float m = -1e30f;
    float l = 0.0f;

    for (int kt = 0; kt <= qb; kt++) {
        __syncthreads();
        {
            const float4* kg = (const float4*)(Kp + (size_t)kt * FBN * HD);
            const float4* vg = (const float4*)(Vp + (size_t)kt * FBN * HD);
            float4* ks4 = (float4*)Ks;
            float4* vs4 = (float4*)Vs;
#pragma unroll
            for (int i = 0; i < 16; i++) {
                ks4[i * 64 + t] = kg[i * 64 + t];
                vs4[i * 64 + t] = vg[i * 64 + t];
            }
        }
        __syncthreads();

#pragma unroll 1
        for (int c = 0; c < 4; c++) {
            float sc[16];
#pragma unroll
            for (int j = 0; j < 16; j++) {
                const int jj = c * 16 + j;
                const float4* kr = (const float4*)(Ks + jj * HD);
                float a0 = 0.f, a1 = 0.f, a2 = 0.f, a3 = 0.f;
#pragma unroll
                for (int d4 = 0; d4 < 16; d4++) {
                    float4 kv = kr[d4];
                    a0 = fmaf(q[4 * d4 + 0], kv.x, a0);
                    a1 = fmaf(q[4 * d4 + 1], kv.y, a1);
                    a2 = fmaf(q[4 * d4 + 2], kv.z, a2);
                    a3 = fmaf(q[4 * d4 + 3], kv.w, a3);
                }
                const int kidx = kt * FBN + jj;
                sc[j] = (kidx <= qidx) ? (a0 + a1 + a2 + a3) * 0.125f : -1e30f;
            }
            float mloc = sc[0];
#pragma unroll
            for (int j = 1; j < 16; j++) mloc = fmaxf(mloc, sc[j]);
            const float mnew = fmaxf(m, mloc);
            const float corr = __expf(m - mnew);
            m = mnew;
            l *= corr;
#pragma unroll
            for (int d = 0; d < HD; d++) o[d] *= corr;
#pragma unroll
            for (int j = 0; j < 16; j++) {
                const float p = __expf(sc[j] - mnew);
                l += p;
                const float4* vr = (const float4*)(Vs + (c * 16 + j) * HD);
#pragma unroll
                for (int d4 = 0; d4 < 16; d4++) {
                    float4 vv = vr[d4];
                    o[4 * d4 + 0] = fmaf(p, vv.x, o[4 * d4 + 0]);
                    o[4 * d4 + 1] = fmaf(p, vv.y, o[4 * d4 + 1]);
                    o[4 * d4 + 2] = fmaf(p, vv.z, o[4 * d4 + 2]);
                    o[4 * d4 + 3] = fmaf(p, vv.w, o[4 * d4 + 3]);
                }
            }
        }
    }

    const float inv = 1.0f / l;
    const int b = bh >> 4;
    const int h = bh & 15;
    const size_t off = ((size_t)(b * SS + qidx)) * DD + h * HD;
    uint32_t ph[32], pl[32];
#pragma unroll
    for (int j = 0; j < 32; j++) {
        const float a = o[2 * j] * inv;
        const float bb2 = o[2 * j + 1] * inv;
        __nv_bfloat16 ha = __float2bfloat16(a);
        __nv_bfloat16 hb = __float2bfloat16(bb2);
        __nv_bfloat16 la = __float2bfloat16(a - __bfloat162float(ha));
        __nv_bfloat16 lb = __float2bfloat16(bb2 - __bfloat162float(hb));
        ph[j] = pk2(ha, hb);
        pl[j] = pk2(la, lb);
    }
    uint4* dh = (uint4*)(ctx_h + off);
    uint4* dl = (uint4*)(ctx_l + off);
#pragma unroll
    for (int k4 = 0; k4 < 8; k4++) {
        dh[k4] = make_uint4(ph[4 * k4], ph[4 * k4 + 1], ph[4 * k4 + 2], ph[4 * k4 + 3]);
        dl[k4] = make_uint4(pl[4 * k4], pl[4 * k4 + 1], pl[4 * k4 + 2], pl[4 * k4 + 3]);
    }
}

// ---------------------------------------------------------------------------
// Launch
// ---------------------------------------------------------------------------
extern "C" void kernel_launch(void* const* d_in, const int* in_sizes, int n_in,
                              void* d_out, int out_size)
{
    const float* x    = (const float*)d_in[0];
    const float* cosb = (const float*)d_in[2];
    const float* sinb = (const float*)d_in[3];
    const float* Wq = (const float*)d_in[4];
    const float* bq = (const float*)d_in[5];
    const float* Wk = (const float*)d_in[6];
    const float* bk = (const float*)d_in[7];
    const float* Wv = (const float*)d_in[8];
    const float* bv = (const float*)d_in[9];
    const float* Wo = (const float*)d_in[10];
    const float* bo = (const float*)d_in[11];
    float* out = (float*)d_out;

    float *Qb, *Kb, *Vb;
    __nv_bfloat16 *xh, *xl, *wh, *wl, *ch, *cl;
    cudaGetSymbolAddress((void**)&Qb, g_Q);
    cudaGetSymbolAddress((void**)&Kb, g_K);
    cudaGetSymbolAddress((void**)&Vb, g_V);
    cudaGetSymbolAddress((void**)&xh, g_xh);
    cudaGetSymbolAddress((void**)&xl, g_xl);
    cudaGetSymbolAddress((void**)&wh, g_wh);
    cudaGetSymbolAddress((void**)&wl, g_wl);
    cudaGetSymbolAddress((void**)&ch, g_ch);
    cudaGetSymbolAddress((void**)&cl, g_cl);

    cudaFuncSetAttribute(gemm_mma, cudaFuncAttributeMaxDynamicSharedMemorySize, GEMM_SMEM);

    // Split x and the 4 weight matrices into bf16 hi/lo
    {
        int n4 = MROWS * DD / 4;
        split_kernel<<<(n4 + 255) / 256, 256>>>((const float4*)x, (uint2*)xh, (uint2*)xl, n4);
        const float* Ws[4] = {Wq, Wk, Wv, Wo};
        int w4 = DD * DD / 4;
        for (int i = 0; i < 4; i++)
            split_kernel<<<(w4 + 255) / 256, 256>>>((const float4*)Ws[i],
                (uint2*)(wh + (size_t)i * DD * DD), (uint2*)(wl + (size_t)i * DD * DD), w4);
    }

    dim3 gg(DD / 128, MROWS / 128);   // (8, 64)
    gemm_mma<<<gg, 256, GEMM_SMEM>>>(xh, xl, wh + 0 * (size_t)DD * DD, wl + 0 * (size_t)DD * DD, bq, Qb, 1);
    gemm_mma<<<gg, 256, GEMM_SMEM>>>(xh, xl, wh + 1 * (size_t)DD * DD, wl + 1 * (size_t)DD * DD, bk, Kb, 1);
    gemm_mma<<<gg, 256, GEMM_SMEM>>>(xh, xl, wh + 2 * (size_t)DD * DD, wl + 2 * (size_t)DD * DD, bv, Vb, 1);

    const int rope_threads = BB * HH * SS * 32;
    rope_kernel<<<rope_threads / 256, 256>>>(Qb, cosb, sinb);
    rope_kernel<<<rope_threads / 256, 256>>>(Kb, cosb, sinb);

    dim3 fg(SS / FBM, BB * HH);       // (32, 64)
    flash_kernel<<<fg, 64>>>(Qb, Kb, Vb, ch, cl);

    gemm_mma<<<gg, 256, GEMM_SMEM>>>(ch, cl, wh + 3 * (size_t)DD * DD, wl + 3 * (size_t)DD * DD, bo, out, 0);
}

// round 5
// speedup vs baseline: 3.3397x; 2.2033x over previous
#include <cuda_runtime.h>
#include <cuda_bf16.h>
#include <math.h>
#include <stdint.h>

// Problem constants
#define BB 4
#define SS 2048
#define DD 1024
#define HH 16
#define HD 64
#define MROWS (BB * SS)   // 8192

// ---------------------------------------------------------------------------
// Scratch (device globals: allocation-free)
// ---------------------------------------------------------------------------
__device__ float g_Q[BB * HH * SS * HD];
__device__ float g_K[BB * HH * SS * HD];
__device__ float g_V[BB * HH * SS * HD];
__device__ __align__(16) __nv_bfloat16 g_xh[MROWS * DD];
__device__ __align__(16) __nv_bfloat16 g_xl[MROWS * DD];
__device__ __align__(16) __nv_bfloat16 g_wh[4 * DD * DD];
__device__ __align__(16) __nv_bfloat16 g_wl[4 * DD * DD];
__device__ __align__(16) __nv_bfloat16 g_ch[MROWS * DD];
__device__ __align__(16) __nv_bfloat16 g_cl[MROWS * DD];
__device__ __align__(16) __nv_bfloat16 g_qh[BB * HH * SS * HD];
__device__ __align__(16) __nv_bfloat16 g_ql[BB * HH * SS * HD];
__device__ __align__(16) __nv_bfloat16 g_kh[BB * HH * SS * HD];
__device__ __align__(16) __nv_bfloat16 g_kl[BB * HH * SS * HD];
__device__ __align__(16) __nv_bfloat16 g_vh[BB * HH * SS * HD];
__device__ __align__(16) __nv_bfloat16 g_vl[BB * HH * SS * HD];

// ---------------------------------------------------------------------------
// Helpers
// ---------------------------------------------------------------------------
__device__ __forceinline__ uint32_t smem_u32(const void* p) {
    uint32_t a;
    asm("{ .reg .u64 t; cvta.to.shared.u64 t, %1; cvt.u32.u64 %0, t; }"
        : "=r"(a) : "l"(p));
    return a;
}

__device__ __forceinline__ void ldsm4(uint32_t* r, uint32_t addr) {
    asm volatile("ldmatrix.sync.aligned.m8n8.x4.shared.b16 {%0,%1,%2,%3}, [%4];"
                 : "=r"(r[0]), "=r"(r[1]), "=r"(r[2]), "=r"(r[3]) : "r"(addr));
}
__device__ __forceinline__ void ldsm4t(uint32_t* r, uint32_t addr) {
    asm volatile("ldmatrix.sync.aligned.m8n8.x4.trans.shared.b16 {%0,%1,%2,%3}, [%4];"
                 : "=r"(r[0]), "=r"(r[1]), "=r"(r[2]), "=r"(r[3]) : "r"(addr));
}

__device__ __forceinline__ void mma16816(float* c, const uint32_t* a, const uint32_t* b) {
    asm volatile("mma.sync.aligned.m16n8k16.row.col.f32.bf16.bf16.f32 "
                 "{%0,%1,%2,%3}, {%4,%5,%6,%7}, {%8,%9}, {%0,%1,%2,%3};"
                 : "+f"(c[0]), "+f"(c[1]), "+f"(c[2]), "+f"(c[3])
                 : "r"(a[0]), "r"(a[1]), "r"(a[2]), "r"(a[3]), "r"(b[0]), "r"(b[1]));
}

#define CP_ASYNC16(dst, src) \
    asm volatile("cp.async.cg.shared.global [%0], [%1], 16;" :: "r"(dst), "l"(src))
#define CP_COMMIT() asm volatile("cp.async.commit_group;" ::: "memory")
#define CP_WAIT0() asm volatile("cp.async.wait_group 0;" ::: "memory")
#define CP_WAIT1() asm volatile("cp.async.wait_group 1;" ::: "memory")

__device__ __forceinline__ uint32_t pk2(__nv_bfloat16 a, __nv_bfloat16 b) {
    return (uint32_t)__bfloat16_as_ushort(a) | ((uint32_t)__bfloat16_as_ushort(b) << 16);
}
__device__ __forceinline__ void split1(float v, __nv_bfloat16& h, __nv_bfloat16& l) {
    h = __float2bfloat16(v);
    l = __float2bfloat16(v - __bfloat162float(h));
}

// ---------------------------------------------------------------------------
// fp32 -> (bf16 hi, bf16 lo) split, vectorized x4
// ---------------------------------------------------------------------------
__global__ __launch_bounds__(256) void split_kernel(
    const float4* __restrict__ src, uint2* __restrict__ hi, uint2* __restrict__ lo, int n4)
{
    int i = blockIdx.x * blockDim.x + threadIdx.x;
    if (i >= n4) return;
    float4 v = src[i];
    __nv_bfloat16 h0, h1, h2, h3, l0, l1, l2, l3;
    split1(v.x, h0, l0); split1(v.y, h1, l1);
    split1(v.z, h2, l2); split1(v.w, h3, l3);
    hi[i] = make_uint2(pk2(h0, h1), pk2(h2, h3));
    lo[i] = make_uint2(pk2(l0, l1), pk2(l2, l3));
}

// ---------------------------------------------------------------------------
// RoPE + bf16 hi/lo split: fp32 [B,H,S,hd] -> bf16 hi/lo
// ---------------------------------------------------------------------------
__global__ __launch_bounds__(256) void rope_split(
    const float* __restrict__ X, const float* __restrict__ cosb,
    const float* __restrict__ sinb,
    __nv_bfloat16* __restrict__ Xh, __nv_bfloat16* __restrict__ Xl)
{
    const int gid = blockIdx.x * blockDim.x + threadIdx.x;
    const int p = gid & 31;
    const int r = gid >> 5;
    const int s = r & (SS - 1);
    const float c1 = cosb[s * HD + p];
    const float s1 = sinb[s * HD + p];
    const float c2 = cosb[s * HD + p + 32];
    const float s2 = sinb[s * HD + p + 32];
    const float* row = X + (size_t)r * HD;
    const float x1 = row[p];
    const float x2 = row[p + 32];
    const float v1 = x1 * c1 - x2 * s1;
    const float v2 = x2 * c2 + x1 * s2;
    __nv_bfloat16 h, l;
    split1(v1, h, l);
    Xh[(size_t)r * HD + p] = h; Xl[(size_t)r * HD + p] = l;
    split1(v2, h, l);
    Xh[(size_t)r * HD + p + 32] = h; Xl[(size_t)r * HD + p + 32] = l;
}

// ---------------------------------------------------------------------------
// HMMA bf16-split GEMM (NT) with cp.async pipeline.
// ---------------------------------------------------------------------------
#define GK 32
#define NCHUNK (DD / GK)       // 32
#define ROWB 80
#define TILE_SB (128 * ROWB)   // 10240
#define BUF_SB (4 * TILE_SB)   // 40960
#define GEMM_SMEM (2 * BUF_SB) // 81920

__global__ __launch_bounds__(256) void gemm_mma(
    const __nv_bfloat16* __restrict__ Ah, const __nv_bfloat16* __restrict__ Al,
    const __nv_bfloat16* __restrict__ Bh, const __nv_bfloat16* __restrict__ Bl,
    const float* __restrict__ bias, float* __restrict__ C, int mode)
{
    extern __shared__ char sm[];
    const int tid  = threadIdx.x;
    const int wid  = tid >> 5;
    const int lane = tid & 31;
    const int bm = blockIdx.y * 128;
    const int bn = blockIdx.x * 128;
    const int warp_m = (wid & 1) * 64;
    const int warp_n = (wid >> 1) * 32;

    const uint32_t sb = smem_u32(sm);

    const char* gsrc[4] = {
        (const char*)(Ah + (size_t)bm * DD), (const char*)(Al + (size_t)bm * DD),
        (const char*)(Bh + (size_t)bn * DD), (const char*)(Bl + (size_t)bn * DD) };

    float acc[4][4][4];
#pragma unroll
    for (int i = 0; i < 4; i++)
#pragma unroll
        for (int j = 0; j < 4; j++)
#pragma unroll
            for (int q = 0; q < 4; q++) acc[i][j][q] = 0.0f;

    auto issue_chunk = [&](int c, int buf) {
        const int koff = c * 64;
        const uint32_t sdst = sb + buf * BUF_SB;
#pragma unroll
        for (int t = 0; t < 4; t++) {
            const char* g = gsrc[t] + koff;
#pragma unroll
            for (int i = 0; i < 2; i++) {
                int idx = i * 256 + tid;
                int row = idx >> 2, seg = idx & 3;
                CP_ASYNC16(sdst + t * TILE_SB + row * ROWB + seg * 16,
                           g + (size_t)row * 2048 + seg * 16);
            }
        }
    };

    issue_chunk(0, 0);
    CP_COMMIT();

    const int lig = lane & 7;
    const int grp = lane >> 3;

    for (int c = 0; c < NCHUNK; c++) {
        const int cur = c & 1;
        if (c + 1 < NCHUNK) { issue_chunk(c + 1, cur ^ 1); CP_COMMIT(); CP_WAIT1(); }
        else                { CP_WAIT0(); }
        __syncthreads();

        const uint32_t bufb = sb + cur * BUF_SB;
#pragma unroll
        for (int ks = 0; ks < 2; ks++) {
            uint32_t aH[4][4], aL[4][4], bH[2][4], bL[2][4];
            {
                const int arow = warp_m + (grp & 1) * 8 + lig;
                const int aseg = 2 * ks + (grp >> 1);
                const uint32_t aoff = arow * ROWB + aseg * 16;
#pragma unroll
                for (int mi = 0; mi < 4; mi++) {
                    ldsm4(aH[mi], bufb + 0 * TILE_SB + aoff + mi * (16 * ROWB));
                    ldsm4(aL[mi], bufb + 1 * TILE_SB + aoff + mi * (16 * ROWB));
                }
            }
            {
                const int brow = warp_n + (grp >> 1) * 8 + lig;
                const int bseg = 2 * ks + (grp & 1);
                const uint32_t boff = brow * ROWB + bseg * 16;
#pragma unroll
                for (int ni = 0; ni < 2; ni++) {
                    ldsm4(bH[ni], bufb + 2 * TILE_SB + boff + ni * (16 * ROWB));
                    ldsm4(bL[ni], bufb + 3 * TILE_SB + boff + ni * (16 * ROWB));
                }
            }
#pragma unroll
            for (int mi = 0; mi < 4; mi++)
#pragma unroll
                for (int nj = 0; nj < 4; nj++) {
                    const int ni = nj >> 1, pr = (nj & 1) * 2;
                    mma16816(acc[mi][nj], aH[mi], &bH[ni][pr]);
                    mma16816(acc[mi][nj], aH[mi], &bL[ni][pr]);
                    mma16816(acc[mi][nj], aL[mi], &bH[ni][pr]);
                }
        }
        __syncthreads();
    }

    const int mrow = lane >> 2;
    const int ncol = 2 * (lane & 3);
#pragma unroll
    for (int mi = 0; mi < 4; mi++) {
#pragma unroll
        for (int nj = 0; nj < 4; nj++) {
            const int m0 = bm + warp_m + mi * 16 + mrow;
            const int n  = bn + warp_n + nj * 8 + ncol;
            const float b0 = bias[n], b1 = bias[n + 1];
#pragma unroll
            for (int half = 0; half < 2; half++) {
                const int m = m0 + half * 8;
                float2 v;
                v.x = acc[mi][nj][2 * half + 0] + b0;
                v.y = acc[mi][nj][2 * half + 1] + b1;
                float* dst;
                if (mode == 0) {
                    dst = C + (size_t)m * DD + n;
                } else {
                    const int b = m >> 11, s = m & 2047;
                    const int h = n >> 6, hd0 = n & 63;
                    dst = C + (((size_t)(b * HH + h) * SS + s) * HD + hd0);
                }
                *(float2*)dst = v;
            }
        }
    }
}

// ---------------------------------------------------------------------------
// HMMA flash attention (causal). Block = 64 q-rows of one (b,h), 4 warps,
// warp = 16 q-rows. BN=64 key tiles, cp.async double buffered.
// Scores: QhKh+QhKl+QlKh ; PV: PhVh+PhVl+PlVh. Writes ctx bf16 hi/lo.
// ---------------------------------------------------------------------------
#define FROW 144
#define FTILE (64 * FROW)      // 9216
#define FBUF (4 * FTILE)       // 36864: Kh,Kl,Vh,Vl
#define FQOFF (2 * FBUF)       // 73728
#define FSMEM (FQOFF + 2 * FTILE)  // 92160

__global__ __launch_bounds__(128) void flash_mma(
    const __nv_bfloat16* __restrict__ Qh, const __nv_bfloat16* __restrict__ Ql,
    const __nv_bfloat16* __restrict__ Kh, const __nv_bfloat16* __restrict__ Kl,
    const __nv_bfloat16* __restrict__ Vh, const __nv_bfloat16* __restrict__ Vl,
    __nv_bfloat16* __restrict__ ctx_h, __nv_bfloat16* __restrict__ ctx_l)
{
    extern __shared__ char sm[];
    const int tid  = threadIdx.x;
    const int wid  = tid >> 5;      // 0..3
    const int lane = tid & 31;
    const int qb = blockIdx.x;      // 0..31
    const int bh = blockIdx.y;      // 0..63
    const uint32_t sb = smem_u32(sm);
    const size_t bhoff = (size_t)bh * SS * HD;

    const int lig = lane & 7;
    const int grp = lane >> 3;

    auto issue_kv = [&](int kt, int buf) {
        const __nv_bfloat16* srcs[4] = {
            Kh + bhoff + (size_t)kt * 64 * HD, Kl + bhoff + (size_t)kt * 64 * HD,
            Vh + bhoff + (size_t)kt * 64 * HD, Vl + bhoff + (size_t)kt * 64 * HD };
        const uint32_t dbase = sb + buf * FBUF;
#pragma unroll
        for (int t = 0; t < 4; t++) {
            const char* g = (const char*)srcs[t];
#pragma unroll
            for (int i = 0; i < 4; i++) {
                int idx = i * 128 + tid;
                int row = idx >> 3, seg = idx & 7;
                CP_ASYNC16(dbase + t * FTILE + row * FROW + seg * 16,
                           g + row * 128 + seg * 16);
            }
        }
    };

    // KV tile 0 + Q tiles
    issue_kv(0, 0);
    CP_COMMIT();
    {
        const char* qsrc[2] = { (const char*)(Qh + bhoff + (size_t)qb * 64 * HD),
                                (const char*)(Ql + bhoff + (size_t)qb * 64 * HD) };
#pragma unroll
        for (int t = 0; t < 2; t++) {
#pragma unroll
            for (int i = 0; i < 4; i++) {
                int idx = i * 128 + tid;
                int row = idx >> 3, seg = idx & 7;
                CP_ASYNC16(sb + FQOFF + t * FTILE + row * FROW + seg * 16,
                           qsrc[t] + row * 128 + seg * 16);
            }
        }
        CP_COMMIT();
    }
    CP_WAIT0();
    __syncthreads();

    // Q fragments (persistent)
    uint32_t qh_f[4][4], ql_f[4][4];
    {
        const int qrow = wid * 16 + (grp & 1) * 8 + lig;
        const uint32_t qa = sb + FQOFF + qrow * FROW;
#pragma unroll
        for (int kc = 0; kc < 4; kc++) {
            const uint32_t off = (2 * kc + (grp >> 1)) * 16;
            ldsm4(qh_f[kc], qa + off);
            ldsm4(ql_f[kc], qa + FTILE + off);
        }
    }

    float o[8][4];
#pragma unroll
    for (int nt = 0; nt < 8; nt++)
#pragma unroll
        for (int q = 0; q < 4; q++) o[nt][q] = 0.0f;
    float m0 = -1e30f, m1 = -1e30f, l0 = 0.0f, l1 = 0.0f;

    for (int kt = 0; kt <= qb; kt++) {
        const int cur = kt & 1;
        if (kt < qb) { issue_kv(kt + 1, cur ^ 1); CP_COMMIT(); CP_WAIT1(); }
        else         { CP_WAIT0(); }
        __syncthreads();

        const uint32_t kb = sb + cur * FBUF;

        // ---- scores ----
        float sc[8][4];
#pragma unroll
        for (int nt = 0; nt < 8; nt++)
#pragma unroll
            for (int q = 0; q < 4; q++) sc[nt][q] = 0.0f;

#pragma unroll
        for (int kc = 0; kc < 4; kc++) {
            uint32_t kh_f[4][4], kl_f[4][4];
            const int krow = (grp >> 1) * 8 + lig;
            const int kseg = 2 * kc + (grp & 1);
#pragma unroll
            for (int p = 0; p < 4; p++) {
                const uint32_t a = kb + (krow + p * 16) * FROW + kseg * 16;
                ldsm4(kh_f[p], a);
                ldsm4(kl_f[p], a + FTILE);
            }
#pragma unroll
            for (int nt = 0; nt < 8; nt++) {
                const int p = nt >> 1, pr = (nt & 1) * 2;
                mma16816(sc[nt], qh_f[kc], &kh_f[p][pr]);
                mma16816(sc[nt], qh_f[kc], &kl_f[p][pr]);
                mma16816(sc[nt], ql_f[kc], &kh_f[p][pr]);
            }
        }

        // ---- softmax ----
        const int rloc = wid * 16 + (lane >> 2);
#pragma unroll
        for (int nt = 0; nt < 8; nt++)
#pragma unroll
            for (int q = 0; q < 4; q++) sc[nt][q] *= 0.125f;

        if (kt == qb) {
#pragma unroll
            for (int nt = 0; nt < 8; nt++)
#pragma unroll
                for (int q = 0; q < 4; q++) {
                    const int col = nt * 8 + 2 * (lane & 3) + (q & 1);
                    const int row = rloc + ((q >> 1) << 3);
                    if (col > row) sc[nt][q] = -1e30f;
                }
        }

        float mx0 = -1e30f, mx1 = -1e30f;
#pragma unroll
        for (int nt = 0; nt < 8; nt++) {
            mx0 = fmaxf(mx0, fmaxf(sc[nt][0], sc[nt][1]));
            mx1 = fmaxf(mx1, fmaxf(sc[nt][2], sc[nt][3]));
        }
        mx0 = fmaxf(mx0, __shfl_xor_sync(0xffffffff, mx0, 1));
        mx0 = fmaxf(mx0, __shfl_xor_sync(0xffffffff, mx0, 2));
        mx1 = fmaxf(mx1, __shfl_xor_sync(0xffffffff, mx1, 1));
        mx1 = fmaxf(mx1, __shfl_xor_sync(0xffffffff, mx1, 2));

        const float mn0 = fmaxf(m0, mx0);
        const float mn1 = fmaxf(m1, mx1);
        const float c0 = __expf(m0 - mn0);
        const float c1 = __expf(m1 - mn1);
        m0 = mn0; m1 = mn1;
        l0 *= c0; l1 *= c1;
#pragma unroll
        for (int nt = 0; nt < 8; nt++) {
            o[nt][0] *= c0; o[nt][1] *= c0;
            o[nt][2] *= c1; o[nt][3] *= c1;
        }

        uint32_t ph_f[4][4], pl_f[4][4];
#pragma unroll
        for (int nt = 0; nt < 8; nt++) {
            const float p0 = __expf(sc[nt][0] - m0);
            const float p1 = __expf(sc[nt][1] - m0);
            const float p2 = __expf(sc[nt][2] - m1);
            const float p3 = __expf(sc[nt][3] - m1);
            l0 += p0 + p1;
            l1 += p2 + p3;
            __nv_bfloat16 h0, h1, h2, h3, e0, e1, e2, e3;
            split1(p0, h0, e0); split1(p1, h1, e1);
            split1(p2, h2, e2); split1(p3, h3, e3);
            const int kc = nt >> 1, hf = (nt & 1) * 2;
            ph_f[kc][hf + 0] = pk2(h0, h1);
            ph_f[kc][hf + 1] = pk2(h2, h3);
            pl_f[kc][hf + 0] = pk2(e0, e1);
            pl_f[kc][hf + 1] = pk2(e2, e3);
        }

        // ---- PV ----
        const uint32_t vb = kb + 2 * FTILE;
#pragma unroll
        for (int kc = 0; kc < 4; kc++) {
            uint32_t vh_f[4][4], vl_f[4][4];
            const int vrow = kc * 16 + (grp & 1) * 8 + lig;
#pragma unroll
            for (int p = 0; p < 4; p++) {
                const uint32_t a = vb + vrow * FROW + (2 * p + (grp >> 1)) * 16;
                ldsm4t(vh_f[p], a);
                ldsm4t(vl_f[p], a + FTILE);
            }
#pragma unroll
            for (int nt = 0; nt < 8; nt++) {
                const int p = nt >> 1, pr = (nt & 1) * 2;
                mma16816(o[nt], ph_f[kc], &vh_f[p][pr]);
                mma16816(o[nt], ph_f[kc], &vl_f[p][pr]);
                mma16816(o[nt], pl_f[kc], &vh_f[p][pr]);
            }
        }
        __syncthreads();
    }

    // ---- finalize ----
    l0 += __shfl_xor_sync(0xffffffff, l0, 1);
    l0 += __shfl_xor_sync(0xffffffff, l0, 2);
    l1 += __shfl_xor_sync(0xffffffff, l1, 1);
    l1 += __shfl_xor_sync(0xffffffff, l1, 2);
    const float i0 = 1.0f / l0;
    const float i1 = 1.0f / l1;

    const int b = bh >> 4;
    const int h = bh & 15;
    const int s0 = qb * 64 + wid * 16 + (lane >> 2);
    const int s1 = s0 + 8;
#pragma unroll
    for (int nt = 0; nt < 8; nt++) {
        const int col = h * 64 + nt * 8 + 2 * (lane & 3);
        const size_t idx0 = ((size_t)(b * SS + s0)) * DD + col;
        const size_t idx1 = ((size_t)(b * SS + s1)) * DD + col;
        __nv_bfloat16 h0, h1, e0, e1;
        split1(o[nt][0] * i0, h0, e0); split1(o[nt][1] * i0, h1, e1);
        *(uint32_t*)(ctx_h + idx0) = pk2(h0, h1);
        *(uint32_t*)(ctx_l + idx0) = pk2(e0, e1);
        split1(o[nt][2] * i1, h0, e0); split1(o[nt][3] * i1, h1, e1);
        *(uint32_t*)(ctx_h + idx1) = pk2(h0, h1);
        *(uint32_t*)(ctx_l + idx1) = pk2(e0, e1);
    }
}

// ---------------------------------------------------------------------------
// Launch
// ---------------------------------------------------------------------------
extern "C" void kernel_launch(void* const* d_in, const int* in_sizes, int n_in,
                              void* d_out, int out_size)
{
    const float* x    = (const float*)d_in[0];
    const float* cosb = (const float*)d_in[2];
    const float* sinb = (const float*)d_in[3];
    const float* Wq = (const float*)d_in[4];
    const float* bq = (const float*)d_in[5];
    const float* Wk = (const float*)d_in[6];
    const float* bk = (const float*)d_in[7];
    const float* Wv = (const float*)d_in[8];
    const float* bv = (const float*)d_in[9];
    const float* Wo = (const float*)d_in[10];
    const float* bo = (const float*)d_in[11];
    float* out = (float*)d_out;

    float *Qb, *Kb, *Vb;
    __nv_bfloat16 *xh, *xl, *wh, *wl, *ch, *cl, *qh, *ql, *kh, *kl, *vh, *vl;
    cudaGetSymbolAddress((void**)&Qb, g_Q);
    cudaGetSymbolAddress((void**)&Kb, g_K);
    cudaGetSymbolAddress((void**)&Vb, g_V);
    cudaGetSymbolAddress((void**)&xh, g_xh);
    cudaGetSymbolAddress((void**)&xl, g_xl);
    cudaGetSymbolAddress((void**)&wh, g_wh);
    cudaGetSymbolAddress((void**)&wl, g_wl);
    cudaGetSymbolAddress((void**)&ch, g_ch);
    cudaGetSymbolAddress((void**)&cl, g_cl);
    cudaGetSymbolAddress((void**)&qh, g_qh);
    cudaGetSymbolAddress((void**)&ql, g_ql);
    cudaGetSymbolAddress((void**)&kh, g_kh);
    cudaGetSymbolAddress((void**)&kl, g_kl);
    cudaGetSymbolAddress((void**)&vh, g_vh);
    cudaGetSymbolAddress((void**)&vl, g_vl);

    cudaFuncSetAttribute(gemm_mma, cudaFuncAttributeMaxDynamicSharedMemorySize, GEMM_SMEM);
    cudaFuncSetAttribute(flash_mma, cudaFuncAttributeMaxDynamicSharedMemorySize, FSMEM);

    {
        int n4 = MROWS * DD / 4;
        split_kernel<<<(n4 + 255) / 256, 256>>>((const float4*)x, (uint2*)xh, (uint2*)xl, n4);
        const float* Ws[4] = {Wq, Wk, Wv, Wo};
        int w4 = DD * DD / 4;
        for (int i = 0; i < 4; i++)
            split_kernel<<<(w4 + 255) / 256, 256>>>((const float4*)Ws[i],
                (uint2*)(wh + (size_t)i * DD * DD), (uint2*)(wl + (size_t)i * DD * DD), w4);
    }

    dim3 gg(DD / 128, MROWS / 128);   // (8, 64)
    gemm_mma<<<gg, 256, GEMM_SMEM>>>(xh, xl, wh + 0 * (size_t)DD * DD, wl + 0 * (size_t)DD * DD, bq, Qb, 1);
    gemm_mma<<<gg, 256, GEMM_SMEM>>>(xh, xl, wh + 1 * (size_t)DD * DD, wl + 1 * (size_t)DD * DD, bk, Kb, 1);
    gemm_mma<<<gg, 256, GEMM_SMEM>>>(xh, xl, wh + 2 * (size_t)DD * DD, wl + 2 * (size_t)DD * DD, bv, Vb, 1);

    const int rope_threads = BB * HH * SS * 32;
    rope_split<<<rope_threads / 256, 256>>>(Qb, cosb, sinb, qh, ql);
    rope_split<<<rope_threads / 256, 256>>>(Kb, cosb, sinb, kh, kl);
    {
        int n4 = BB * HH * SS * HD / 4;
        split_kernel<<<(n4 + 255) / 256, 256>>>((const float4*)Vb, (uint2*)vh, (uint2*)vl, n4);
    }

    dim3 fg(SS / 64, BB * HH);        // (32, 64)
    flash_mma<<<fg, 128, FSMEM>>>(qh, ql, kh, kl, vh, vl, ch, cl);

    gemm_mma<<<gg, 256, GEMM_SMEM>>>(ch, cl, wh + 3 * (size_t)DD * DD, wl + 3 * (size_t)DD * DD, bo, out, 0);
}